// round 7
// baseline (speedup 1.0000x reference)
#include <cuda_runtime.h>
#include <stdint.h>

#define BB 16
#define CC 19
#define HH 512
#define WW 512
#define KX 4
#define WSEG 4            // 512 / (32*KX)
#define HCH 8
#define HROWS (HH/HCH)    // 64
#define WPB 4             // warps per block (128 threads)
#define NWARPS (BB*CC*WSEG*HCH)   // 9728
#define NBLOCKS (NWARPS/WPB)      // 2432

#define B01   0x01010101u
#define BIAS4 0x04040404u

__device__ unsigned char g_tgt8[BB*HH*WW];  // 4 MB scratch (static, allowed)
__device__ double g_acc;                     // zero-init; edge's last block resets
__device__ unsigned g_ticket;

// ---------------------------------------------------------------------------
// prep: detect int64-vs-int32 targets and convert to uint8 (L2-resident for
// the 19x channel reuse). Sampling is safe for the SMALLEST possible buffer
// (int32: 4,194,304 words). int64 -> all odd words zero; int32 -> odd words
// are labels, P(all 16 samples == 0) = 19^-16 ~ 0.
// ---------------------------------------------------------------------------
__global__ void prep_kernel(const unsigned int* __restrict__ t) {
    bool is32 = false;
    #pragma unroll
    for (unsigned k = 0; k < 16; k++) {
        unsigned idx = k * 262139u + 1u;       // max 3,932,086 < 4,194,304
        is32 |= (__ldg(&t[idx | 1u]) != 0u);   // force odd
    }

    const int n4 = BB * HH * WW / 4;
    for (int i = blockIdx.x * blockDim.x + threadIdx.x; i < n4;
         i += gridDim.x * blockDim.x) {
        uchar4 o;
        if (is32) {
            uint4 v = reinterpret_cast<const uint4*>(t)[i];
            o.x = (unsigned char)v.x; o.y = (unsigned char)v.y;
            o.z = (unsigned char)v.z; o.w = (unsigned char)v.w;
        } else {
            o.x = (unsigned char)t[(4 * i + 0) * 2];
            o.y = (unsigned char)t[(4 * i + 1) * 2];
            o.z = (unsigned char)t[(4 * i + 2) * 2];
            o.w = (unsigned char)t[(4 * i + 3) * 2];
        }
        reinterpret_cast<uchar4*>(g_tgt8)[i] = o;
    }
}

// ---------------------------------------------------------------------------
// Raw row (loads only) and derived per-row separable terms.
// Target terms byte-packed: u biased +1 per byte (in [0,2]), v in [0,4].
// ---------------------------------------------------------------------------
struct Raw  { float x0, x1, x2, x3, xl, xr; unsigned t4, th; };  // th = tl|(tr<<8)
struct RowD { float a[KX], s[KX]; unsigned u, v; };

__device__ __forceinline__ void load_row(
    Raw& r, const float* __restrict__ plane,
    const unsigned char* __restrict__ tplane,
    int row, int w0, int wstart, int lane)
{
    if ((unsigned)row >= (unsigned)HH) {        // warp-uniform
        r.x0 = r.x1 = r.x2 = r.x3 = r.xl = r.xr = 0.f;
        r.t4 = 0xFFFFFFFFu; r.th = 0xFFFFu;     // 255 != any class
        return;
    }
    const float* xrow = plane + (size_t)row * WW;
    float4 xv = *reinterpret_cast<const float4*>(xrow + w0);
    // Warp-uniform broadcast halo loads (no divergence).
    const int la = (wstart > 0) ? (wstart - 1) : 0;
    const int ra = (wstart + 128 < WW) ? (wstart + 128) : (WW - 1);
    float hl = __ldg(xrow + la);
    float hr = __ldg(xrow + ra);
    float xsl = __shfl_up_sync(0xffffffffu, xv.w, 1);
    float xsr = __shfl_down_sync(0xffffffffu, xv.x, 1);
    r.xl = (lane == 0)  ? ((wstart > 0)        ? hl : 0.f) : xsl;
    r.xr = (lane == 31) ? ((wstart + 128 < WW) ? hr : 0.f) : xsr;
    r.x0 = xv.x; r.x1 = xv.y; r.x2 = xv.z; r.x3 = xv.w;

    const unsigned char* trow = tplane + (size_t)row * WW;
    unsigned t4 = *reinterpret_cast<const unsigned*>(trow + w0);
    unsigned htl = (unsigned)__ldg(trow + la);
    unsigned htr = (unsigned)__ldg(trow + ra);
    unsigned tsl = __shfl_up_sync(0xffffffffu, t4, 1) >> 24;
    unsigned tsr = __shfl_down_sync(0xffffffffu, t4, 1) & 0xFFu;
    unsigned tl = (lane == 0)  ? ((wstart > 0)        ? htl : 0xFFu) : tsl;
    unsigned tr = (lane == 31) ? ((wstart + 128 < WW) ? htr : 0xFFu) : tsr;
    r.t4 = t4; r.th = tl | (tr << 8);
}

__device__ __forceinline__ void derive(RowD& d, const Raw& r, unsigned cc4) {
    // input: diff-x / smooth-x
    d.a[0] = r.x1 - r.xl;  d.a[1] = r.x2 - r.x0;
    d.a[2] = r.x3 - r.x1;  d.a[3] = r.xr - r.x2;
    d.s[0] = fmaf(2.f, r.x0, r.xl + r.x1);
    d.s[1] = fmaf(2.f, r.x1, r.x0 + r.x2);
    d.s[2] = fmaf(2.f, r.x2, r.x1 + r.x3);
    d.s[3] = fmaf(2.f, r.x3, r.x2 + r.xr);
    // target: byte-SIMD masks on shifted windows
    unsigned m01  = __vcmpeq4(r.t4, cc4) & B01;
    unsigned l4   = __byte_perm(r.t4, r.th, 0x2104);  // (tl, t0, t1, t2)
    unsigned r4   = __byte_perm(r.t4, r.th, 0x5321);  // (t1, t2, t3, tr)
    unsigned ml01 = __vcmpeq4(l4, cc4) & B01;
    unsigned mr01 = __vcmpeq4(r4, cc4) & B01;
    d.u = (mr01 + B01) - ml01;            // per-byte u+1, in [0,2]; no borrow
    d.v = ml01 + mr01 + (m01 << 1);       // per-byte, in [0,4]; no carry
}

__device__ __forceinline__ void emit_row(
    const RowD& P, const RowD& C0, const RowD& N, float& acc)
{
    // Target edge magnitude fully in byte domain:
    //   gxt_b per byte = P.u+N.u+2*C0.u, biased +4, in [0,8]  -> |gxt| via vabsdiff
    //   |gyt| = |N.v - P.v| via vabsdiff (no bias needed)
    //   etg per byte <= 8 -> carry-free add
    unsigned gxt_b = P.u + N.u + (C0.u << 1);
    unsigned etg_b = __vabsdiffu4(gxt_b, BIAS4) + __vabsdiffu4(N.v, P.v);
    #pragma unroll
    for (int i = 0; i < KX; i++) {
        float gx  = fmaf(2.f, C0.a[i], P.a[i] + N.a[i]);
        float gy  = N.s[i] - P.s[i];
        float ein = fabsf(gx) + fabsf(gy);
        // byte i -> exact float via mantissa insertion (one PRMT + one FSUB)
        float etg = __uint_as_float(
            __byte_perm(etg_b, 0x4B000000u, 0x7440u + (unsigned)i)) - 8388608.0f;
        float d = ein - etg;
        acc = fmaf(d, d, acc);
    }
}

__global__ __launch_bounds__(WPB * 32, 6)
void edge_kernel(const float* __restrict__ inp, float* __restrict__ out)
{
    const int warp = blockIdx.x * WPB + (threadIdx.x >> 5);
    const int lane = threadIdx.x & 31;

    const int wseg = warp & (WSEG - 1);
    const int hch  = (warp >> 2) & (HCH - 1);
    const int t2   = warp >> 5;               // = b*CC + c, in [0, 304)
    const unsigned c = (unsigned)(t2 % CC);
    const int b    = t2 / CC;
    const unsigned cc4 = c * 0x01010101u;

    const int wstart = wseg * (32 * KX);
    const int w0 = wstart + lane * KX;
    const int h0 = hch * HROWS;
    const float* plane = inp + ((size_t)t2) * HH * WW;
    const unsigned char* tplane = g_tgt8 + (size_t)b * HH * WW;

    float acc = 0.f;
    RowD rA, rB, rC;
    Raw q0, q1;

    // Prologue: invariant at loop top — q0 holds row y+1, q1 holds row y+2.
    load_row(q0, plane, tplane, h0 - 1, w0, wstart, lane);
    load_row(q1, plane, tplane, h0,     w0, wstart, lane);
    derive(rA, q0, cc4); load_row(q0, plane, tplane, h0 + 1, w0, wstart, lane);
    derive(rB, q1, cc4); load_row(q1, plane, tplane, h0 + 2, w0, wstart, lane);

    int y = h0;
    // 6-phase body (LCM of 2 raw slots x 3 row regs), 10 iters = 60 rows
    #pragma unroll 1
    for (int it = 0; it < 10; ++it) {
        derive(rC, q0, cc4); load_row(q0, plane, tplane, y + 3, w0, wstart, lane);
        emit_row(rA, rB, rC, acc); ++y;
        derive(rA, q1, cc4); load_row(q1, plane, tplane, y + 3, w0, wstart, lane);
        emit_row(rB, rC, rA, acc); ++y;
        derive(rB, q0, cc4); load_row(q0, plane, tplane, y + 3, w0, wstart, lane);
        emit_row(rC, rA, rB, acc); ++y;
        derive(rC, q1, cc4); load_row(q1, plane, tplane, y + 3, w0, wstart, lane);
        emit_row(rA, rB, rC, acc); ++y;
        derive(rA, q0, cc4); load_row(q0, plane, tplane, y + 3, w0, wstart, lane);
        emit_row(rB, rC, rA, acc); ++y;
        derive(rB, q1, cc4); load_row(q1, plane, tplane, y + 3, w0, wstart, lane);
        emit_row(rC, rA, rB, acc); ++y;
    }
    // Epilogue: 4 remaining rows (60..63)
    derive(rC, q0, cc4); load_row(q0, plane, tplane, y + 3, w0, wstart, lane);
    emit_row(rA, rB, rC, acc); ++y;
    derive(rA, q1, cc4); load_row(q1, plane, tplane, y + 3, w0, wstart, lane);
    emit_row(rB, rC, rA, acc); ++y;
    derive(rB, q0, cc4); emit_row(rC, rA, rB, acc); ++y;
    derive(rC, q1, cc4); emit_row(rA, rB, rC, acc);

    // reduce: warp -> block -> global double; last block finalizes + resets.
    #pragma unroll
    for (int o = 16; o; o >>= 1) acc += __shfl_xor_sync(0xffffffffu, acc, o);
    __shared__ float ws[WPB];
    if (lane == 0) ws[threadIdx.x >> 5] = acc;
    __syncthreads();
    if (threadIdx.x == 0) {
        double s = 0.0;
        #pragma unroll
        for (int i = 0; i < WPB; i++) s += (double)ws[i];
        atomicAdd(&g_acc, s);
        __threadfence();
        unsigned t = atomicAdd(&g_ticket, 1u);
        if (t == (unsigned)(NBLOCKS - 1)) {
            double v = atomicAdd(&g_acc, 0.0);   // ordered read
            out[0] = (float)(v * (1.0 / ((double)BB * HH * WW)));
            g_acc = 0.0;                          // reset for next replay
            g_ticket = 0u;
        }
    }
}

// ---------------------------------------------------------------------------
extern "C" void kernel_launch(void* const* d_in, const int* in_sizes, int n_in,
                              void* d_out, int out_size)
{
    const float* inp;
    const unsigned int* tgt;
    if (in_sizes[0] == BB * CC * HH * WW) {
        inp = (const float*)d_in[0];
        tgt = (const unsigned int*)d_in[1];
    } else {
        inp = (const float*)d_in[1];
        tgt = (const unsigned int*)d_in[0];
    }
    float* out = (float*)d_out;

    prep_kernel<<<1184, 256>>>(tgt);
    edge_kernel<<<NBLOCKS, WPB * 32>>>(inp, out);
}

// round 8
// speedup vs baseline: 1.0208x; 1.0208x over previous
#include <cuda_runtime.h>
#include <stdint.h>

#define BB 16
#define CC 19
#define HH 512
#define WW 512
#define KX 4
#define WSEG 4            // 512 / (32*KX)
#define HCH 16
#define HROWS (HH/HCH)    // 32
#define WPB 4             // warps per block (128 threads)
#define NWARPS (BB*CC*WSEG*HCH)   // 19456
#define NBLOCKS (NWARPS/WPB)      // 4864

#define B01   0x01010101u

__device__ unsigned char g_tgt8[BB*HH*WW];  // 4 MB scratch (static, allowed)
__device__ double g_acc;                     // zero-init; edge's last block resets
__device__ unsigned g_ticket;

// ---------------------------------------------------------------------------
// prep: detect int64-vs-int32 targets and convert to uint8 (L2-resident for
// the 19x channel reuse). Sampling safe for the SMALLEST possible buffer
// (int32: 4,194,304 words). int64 -> all odd words zero; int32 -> odd words
// are labels, P(all 16 samples == 0) = 19^-16 ~ 0.
// ---------------------------------------------------------------------------
__global__ void prep_kernel(const unsigned int* __restrict__ t) {
    bool is32 = false;
    #pragma unroll
    for (unsigned k = 0; k < 16; k++) {
        unsigned idx = k * 262139u + 1u;       // max 3,932,086 < 4,194,304
        is32 |= (__ldg(&t[idx | 1u]) != 0u);   // force odd
    }

    const int n4 = BB * HH * WW / 4;
    for (int i = blockIdx.x * blockDim.x + threadIdx.x; i < n4;
         i += gridDim.x * blockDim.x) {
        uchar4 o;
        if (is32) {
            uint4 v = reinterpret_cast<const uint4*>(t)[i];
            o.x = (unsigned char)v.x; o.y = (unsigned char)v.y;
            o.z = (unsigned char)v.z; o.w = (unsigned char)v.w;
        } else {
            o.x = (unsigned char)t[(4 * i + 0) * 2];
            o.y = (unsigned char)t[(4 * i + 1) * 2];
            o.z = (unsigned char)t[(4 * i + 2) * 2];
            o.w = (unsigned char)t[(4 * i + 3) * 2];
        }
        reinterpret_cast<uchar4*>(g_tgt8)[i] = o;
    }
}

// ---------------------------------------------------------------------------
// Raw row (loads only) and derived per-row separable terms.
// Target terms byte-packed: u biased +1 per byte (in [0,2]), v in [0,4].
// ---------------------------------------------------------------------------
struct Raw  { float x0, x1, x2, x3, xl, xr; unsigned t4, th; };  // th = tl|(tr<<8)
struct RowD { float a[KX], s[KX]; unsigned u, v; };

__device__ __forceinline__ void load_row(
    Raw& r, const float* __restrict__ plane,
    const unsigned char* __restrict__ tplane,
    int row, int w0, int wstart, int lane)
{
    if ((unsigned)row >= (unsigned)HH) {        // warp-uniform
        r.x0 = r.x1 = r.x2 = r.x3 = r.xl = r.xr = 0.f;
        r.t4 = 0xFFFFFFFFu; r.th = 0xFFFFu;     // 255 != any class
        return;
    }
    const float* xrow = plane + (size_t)row * WW;
    float4 xv = *reinterpret_cast<const float4*>(xrow + w0);
    // Warp-uniform broadcast halo loads (no divergence, 1 wavefront each).
    const int la = (wstart > 0) ? (wstart - 1) : 0;
    const int ra = (wstart + 128 < WW) ? (wstart + 128) : (WW - 1);
    float hl = __ldg(xrow + la);
    float hr = __ldg(xrow + ra);
    float xsl = __shfl_up_sync(0xffffffffu, xv.w, 1);
    float xsr = __shfl_down_sync(0xffffffffu, xv.x, 1);
    r.xl = (lane == 0)  ? ((wstart > 0)        ? hl : 0.f) : xsl;
    r.xr = (lane == 31) ? ((wstart + 128 < WW) ? hr : 0.f) : xsr;
    r.x0 = xv.x; r.x1 = xv.y; r.x2 = xv.z; r.x3 = xv.w;

    const unsigned char* trow = tplane + (size_t)row * WW;
    unsigned t4 = *reinterpret_cast<const unsigned*>(trow + w0);
    unsigned htl = (unsigned)__ldg(trow + la);
    unsigned htr = (unsigned)__ldg(trow + ra);
    unsigned tsl = __shfl_up_sync(0xffffffffu, t4, 1) >> 24;
    unsigned tsr = __shfl_down_sync(0xffffffffu, t4, 1) & 0xFFu;
    unsigned tl = (lane == 0)  ? ((wstart > 0)        ? htl : 0xFFu) : tsl;
    unsigned tr = (lane == 31) ? ((wstart + 128 < WW) ? htr : 0xFFu) : tsr;
    r.t4 = t4; r.th = tl | (tr << 8);
}

__device__ __forceinline__ void derive(RowD& d, const Raw& r, unsigned cc4) {
    // input: diff-x / smooth-x
    d.a[0] = r.x1 - r.xl;  d.a[1] = r.x2 - r.x0;
    d.a[2] = r.x3 - r.x1;  d.a[3] = r.xr - r.x2;
    d.s[0] = fmaf(2.f, r.x0, r.xl + r.x1);
    d.s[1] = fmaf(2.f, r.x1, r.x0 + r.x2);
    d.s[2] = fmaf(2.f, r.x2, r.x1 + r.x3);
    d.s[3] = fmaf(2.f, r.x3, r.x2 + r.xr);
    // target: byte-SIMD masks on shifted windows
    unsigned m01  = __vcmpeq4(r.t4, cc4) & B01;
    unsigned l4   = __byte_perm(r.t4, r.th, 0x2104);  // (tl, t0, t1, t2)
    unsigned r4   = __byte_perm(r.t4, r.th, 0x5321);  // (t1, t2, t3, tr)
    unsigned ml01 = __vcmpeq4(l4, cc4) & B01;
    unsigned mr01 = __vcmpeq4(r4, cc4) & B01;
    d.u = (mr01 + B01) - ml01;            // per-byte u+1, in [0,2]; no borrow
    d.v = ml01 + mr01 + (m01 << 1);       // per-byte, in [0,4]; no carry
}

__device__ __forceinline__ float unpack_b(unsigned w, unsigned sel) {
    // byte -> exact float via mantissa insertion; subtract (2^23 + bias 4)
    return __uint_as_float(__byte_perm(w, 0x4B000000u, sel)) - 8388612.0f;
}

__device__ __forceinline__ void emit_row(
    const RowD& P, const RowD& C0, const RowD& N, float& acc0, float& acc1)
{
    // packed target gradients, per-byte biased by +4, range [0,8]: carry-free
    unsigned gxt_b = P.u + N.u + (C0.u << 1);
    unsigned gyt_b = (N.v + 0x04040404u) - P.v;
    #pragma unroll
    for (int i = 0; i < KX; i++) {
        float gx  = fmaf(2.f, C0.a[i], P.a[i] + N.a[i]);
        float gy  = N.s[i] - P.s[i];
        float ein = fabsf(gx) + fabsf(gy);
        unsigned sel = 0x7440u + (unsigned)i;
        float etg = fabsf(unpack_b(gxt_b, sel)) + fabsf(unpack_b(gyt_b, sel));
        float d = ein - etg;
        if (i & 1) acc1 = fmaf(d, d, acc1);
        else       acc0 = fmaf(d, d, acc0);
    }
}

__global__ __launch_bounds__(WPB * 32, 6)
void edge_kernel(const float* __restrict__ inp, float* __restrict__ out)
{
    const int warp = blockIdx.x * WPB + (threadIdx.x >> 5);
    const int lane = threadIdx.x & 31;

    const int wseg = warp & (WSEG - 1);
    const int hch  = (warp >> 2) & (HCH - 1);
    const int t2   = warp >> 6;               // = b*CC + c, in [0, 304)
    const unsigned c = (unsigned)(t2 % CC);
    const int b    = t2 / CC;
    const unsigned cc4 = c * 0x01010101u;

    const int wstart = wseg * (32 * KX);
    const int w0 = wstart + lane * KX;
    const int h0 = hch * HROWS;
    const float* plane = inp + ((size_t)t2) * HH * WW;
    const unsigned char* tplane = g_tgt8 + (size_t)b * HH * WW;

    float acc0 = 0.f, acc1 = 0.f;
    RowD rA, rB, rC;
    Raw q0, q1;

    // Prologue: invariant at loop top — q0 holds row y+1, q1 holds row y+2.
    load_row(q0, plane, tplane, h0 - 1, w0, wstart, lane);
    load_row(q1, plane, tplane, h0,     w0, wstart, lane);
    derive(rA, q0, cc4); load_row(q0, plane, tplane, h0 + 1, w0, wstart, lane);
    derive(rB, q1, cc4); load_row(q1, plane, tplane, h0 + 2, w0, wstart, lane);

    int y = h0;
    // 6-phase body, 5 iters = 30 rows; loads reach exactly row h0+32 (max halo)
    #pragma unroll 1
    for (int it = 0; it < 5; ++it) {
        derive(rC, q0, cc4); load_row(q0, plane, tplane, y + 3, w0, wstart, lane);
        emit_row(rA, rB, rC, acc0, acc1); ++y;
        derive(rA, q1, cc4); load_row(q1, plane, tplane, y + 3, w0, wstart, lane);
        emit_row(rB, rC, rA, acc0, acc1); ++y;
        derive(rB, q0, cc4); load_row(q0, plane, tplane, y + 3, w0, wstart, lane);
        emit_row(rC, rA, rB, acc0, acc1); ++y;
        derive(rC, q1, cc4); load_row(q1, plane, tplane, y + 3, w0, wstart, lane);
        emit_row(rA, rB, rC, acc0, acc1); ++y;
        derive(rA, q0, cc4); load_row(q0, plane, tplane, y + 3, w0, wstart, lane);
        emit_row(rB, rC, rA, acc0, acc1); ++y;
        derive(rB, q1, cc4); load_row(q1, plane, tplane, y + 3, w0, wstart, lane);
        emit_row(rC, rA, rB, acc0, acc1); ++y;
    }
    // Epilogue: rows h0+30, h0+31 — no further loads (q0=h0+31, q1=h0+32)
    derive(rC, q0, cc4); emit_row(rA, rB, rC, acc0, acc1);
    derive(rA, q1, cc4); emit_row(rB, rC, rA, acc0, acc1);

    // reduce: warp -> block -> global double; last block finalizes + resets.
    float acc = acc0 + acc1;
    #pragma unroll
    for (int o = 16; o; o >>= 1) acc += __shfl_xor_sync(0xffffffffu, acc, o);
    __shared__ float ws[WPB];
    if (lane == 0) ws[threadIdx.x >> 5] = acc;
    __syncthreads();
    if (threadIdx.x == 0) {
        double s = 0.0;
        #pragma unroll
        for (int i = 0; i < WPB; i++) s += (double)ws[i];
        atomicAdd(&g_acc, s);
        __threadfence();
        unsigned t = atomicAdd(&g_ticket, 1u);
        if (t == (unsigned)(NBLOCKS - 1)) {
            double v = atomicAdd(&g_acc, 0.0);   // ordered read
            out[0] = (float)(v * (1.0 / ((double)BB * HH * WW)));
            g_acc = 0.0;                          // reset for next replay
            g_ticket = 0u;
        }
    }
}

// ---------------------------------------------------------------------------
extern "C" void kernel_launch(void* const* d_in, const int* in_sizes, int n_in,
                              void* d_out, int out_size)
{
    const float* inp;
    const unsigned int* tgt;
    if (in_sizes[0] == BB * CC * HH * WW) {
        inp = (const float*)d_in[0];
        tgt = (const unsigned int*)d_in[1];
    } else {
        inp = (const float*)d_in[1];
        tgt = (const unsigned int*)d_in[0];
    }
    float* out = (float*)d_out;

    prep_kernel<<<1184, 256>>>(tgt);
    edge_kernel<<<NBLOCKS, WPB * 32>>>(inp, out);
}

// round 9
// speedup vs baseline: 1.3045x; 1.2779x over previous
#include <cuda_runtime.h>
#include <stdint.h>

#define BB 16
#define CC 19
#define HH 512
#define WW 512
#define KX 4
#define WSEG 4            // 512 / (32*KX)
#define HCH 8
#define HROWS (HH/HCH)    // 64
#define WPB 4             // warps per block (128 threads)
#define NWARPS (BB*CC*WSEG*HCH)   // 9728
#define NBLOCKS (NWARPS/WPB)      // 2432

#define B01   0x01010101u

__device__ unsigned char g_tgt8[BB*HH*WW];  // 4 MB scratch (static, allowed)
__device__ double g_acc;                     // zero-init; edge's last block resets
__device__ unsigned g_ticket;

// ---------------------------------------------------------------------------
// prep: detect int64-vs-int32 targets and convert to uint8 (L2-resident for
// the 19x channel reuse). Sampling safe for the SMALLEST possible buffer
// (int32: 4,194,304 words). int64 -> all odd words zero; int32 -> odd words
// are labels, P(all 16 samples == 0) = 19^-16 ~ 0.
// ---------------------------------------------------------------------------
__global__ void prep_kernel(const unsigned int* __restrict__ t) {
    bool is32 = false;
    #pragma unroll
    for (unsigned k = 0; k < 16; k++) {
        unsigned idx = k * 262139u + 1u;       // max 3,932,086 < 4,194,304
        is32 |= (__ldg(&t[idx | 1u]) != 0u);   // force odd
    }

    const int n4 = BB * HH * WW / 4;
    for (int i = blockIdx.x * blockDim.x + threadIdx.x; i < n4;
         i += gridDim.x * blockDim.x) {
        uchar4 o;
        if (is32) {
            uint4 v = reinterpret_cast<const uint4*>(t)[i];
            o.x = (unsigned char)v.x; o.y = (unsigned char)v.y;
            o.z = (unsigned char)v.z; o.w = (unsigned char)v.w;
        } else {
            o.x = (unsigned char)t[(4 * i + 0) * 2];
            o.y = (unsigned char)t[(4 * i + 1) * 2];
            o.z = (unsigned char)t[(4 * i + 2) * 2];
            o.w = (unsigned char)t[(4 * i + 3) * 2];
        }
        reinterpret_cast<uchar4*>(g_tgt8)[i] = o;
    }
}

// ---------------------------------------------------------------------------
// Raw row (loads only; halos via direct L1-hit neighbor loads, no shuffles)
// and derived per-row separable terms.
// Target terms byte-packed: u biased +1 per byte (in [0,2]), v in [0,4].
// ---------------------------------------------------------------------------
struct Raw  { float x0, x1, x2, x3, xl, xr; unsigned t4, th; };  // th = tl|(tr<<8)
struct RowD { float a[KX], s[KX]; unsigned u, v; };

__device__ __forceinline__ void load_row(
    Raw& r, const float* __restrict__ plane,
    const unsigned char* __restrict__ tplane,
    int row, int w0, int offL, int offR, bool lok, bool rok)
{
    if ((unsigned)row >= (unsigned)HH) {        // warp-uniform
        r.x0 = r.x1 = r.x2 = r.x3 = r.xl = r.xr = 0.f;
        r.t4 = 0xFFFFFFFFu; r.th = 0xFFFFu;     // 255 != any class
        return;
    }
    const float* xrow = plane + (size_t)row * WW;
    float4 xv = *reinterpret_cast<const float4*>(xrow + w0);
    // Neighbor-element halo loads: same L1 lines as the float4s -> hits.
    // Offsets are pre-clamped in-bounds; value selected at boundaries.
    float hl = __ldg(xrow + offL);
    float hr = __ldg(xrow + offR);
    r.xl = lok ? hl : 0.f;
    r.xr = rok ? hr : 0.f;
    r.x0 = xv.x; r.x1 = xv.y; r.x2 = xv.z; r.x3 = xv.w;

    const unsigned char* trow = tplane + (size_t)row * WW;
    unsigned t4 = *reinterpret_cast<const unsigned*>(trow + w0);
    unsigned tl = (unsigned)__ldg(trow + offL);
    unsigned tr = (unsigned)__ldg(trow + offR);
    r.t4 = t4;
    r.th = (lok ? tl : 0xFFu) | ((rok ? tr : 0xFFu) << 8);
}

__device__ __forceinline__ void derive(RowD& d, const Raw& r, unsigned cc4) {
    // input: diff-x / smooth-x
    d.a[0] = r.x1 - r.xl;  d.a[1] = r.x2 - r.x0;
    d.a[2] = r.x3 - r.x1;  d.a[3] = r.xr - r.x2;
    d.s[0] = fmaf(2.f, r.x0, r.xl + r.x1);
    d.s[1] = fmaf(2.f, r.x1, r.x0 + r.x2);
    d.s[2] = fmaf(2.f, r.x2, r.x1 + r.x3);
    d.s[3] = fmaf(2.f, r.x3, r.x2 + r.xr);
    // target: byte-SIMD masks on shifted windows
    unsigned m01  = __vcmpeq4(r.t4, cc4) & B01;
    unsigned l4   = __byte_perm(r.t4, r.th, 0x2104);  // (tl, t0, t1, t2)
    unsigned r4   = __byte_perm(r.t4, r.th, 0x5321);  // (t1, t2, t3, tr)
    unsigned ml01 = __vcmpeq4(l4, cc4) & B01;
    unsigned mr01 = __vcmpeq4(r4, cc4) & B01;
    d.u = (mr01 + B01) - ml01;            // per-byte u+1, in [0,2]; no borrow
    d.v = ml01 + mr01 + (m01 << 1);       // per-byte, in [0,4]; no carry
}

__device__ __forceinline__ float unpack_b(unsigned w, unsigned sel) {
    // byte -> exact float via mantissa insertion; subtract (2^23 + bias 4)
    return __uint_as_float(__byte_perm(w, 0x4B000000u, sel)) - 8388612.0f;
}

__device__ __forceinline__ void emit_row(
    const RowD& P, const RowD& C0, const RowD& N, float& acc0, float& acc1)
{
    // packed target gradients, per-byte biased by +4, range [0,8]: carry-free
    unsigned gxt_b = P.u + N.u + (C0.u << 1);
    unsigned gyt_b = (N.v + 0x04040404u) - P.v;
    #pragma unroll
    for (int i = 0; i < KX; i++) {
        float gx  = fmaf(2.f, C0.a[i], P.a[i] + N.a[i]);
        float gy  = N.s[i] - P.s[i];
        float ein = fabsf(gx) + fabsf(gy);
        unsigned sel = 0x7440u + (unsigned)i;
        float etg = fabsf(unpack_b(gxt_b, sel)) + fabsf(unpack_b(gyt_b, sel));
        float d = ein - etg;
        if (i & 1) acc1 = fmaf(d, d, acc1);
        else       acc0 = fmaf(d, d, acc0);
    }
}

__global__ __launch_bounds__(WPB * 32, 6)
void edge_kernel(const float* __restrict__ inp, float* __restrict__ out)
{
    const int warp = blockIdx.x * WPB + (threadIdx.x >> 5);
    const int lane = threadIdx.x & 31;

    const int wseg = warp & (WSEG - 1);
    const int hch  = (warp >> 2) & (HCH - 1);
    const int t2   = warp >> 5;               // = b*CC + c, in [0, 304)
    const unsigned c = (unsigned)(t2 % CC);
    const int b    = t2 / CC;
    const unsigned cc4 = c * 0x01010101u;

    const int wstart = wseg * (32 * KX);
    const int w0 = wstart + lane * KX;
    const bool lok = (w0 > 0);
    const bool rok = (w0 + KX < WW);
    const int offL = lok ? (w0 - 1)  : w0;    // clamped in-bounds
    const int offR = rok ? (w0 + KX) : w0;
    const int h0 = hch * HROWS;
    const float* plane = inp + ((size_t)t2) * HH * WW;
    const unsigned char* tplane = g_tgt8 + (size_t)b * HH * WW;

    float acc0 = 0.f, acc1 = 0.f;
    RowD rA, rB, rC;
    Raw q0, q1;

    // Prologue: invariant at loop top — q0 holds row y+1, q1 holds row y+2.
    load_row(q0, plane, tplane, h0 - 1, w0, offL, offR, lok, rok);
    load_row(q1, plane, tplane, h0,     w0, offL, offR, lok, rok);
    derive(rA, q0, cc4); load_row(q0, plane, tplane, h0 + 1, w0, offL, offR, lok, rok);
    derive(rB, q1, cc4); load_row(q1, plane, tplane, h0 + 2, w0, offL, offR, lok, rok);

    int y = h0;
    // 6-phase body (LCM of 2 raw slots x 3 row regs), 10 iters = 60 rows
    #pragma unroll 1
    for (int it = 0; it < 10; ++it) {
        derive(rC, q0, cc4); load_row(q0, plane, tplane, y + 3, w0, offL, offR, lok, rok);
        emit_row(rA, rB, rC, acc0, acc1); ++y;
        derive(rA, q1, cc4); load_row(q1, plane, tplane, y + 3, w0, offL, offR, lok, rok);
        emit_row(rB, rC, rA, acc0, acc1); ++y;
        derive(rB, q0, cc4); load_row(q0, plane, tplane, y + 3, w0, offL, offR, lok, rok);
        emit_row(rC, rA, rB, acc0, acc1); ++y;
        derive(rC, q1, cc4); load_row(q1, plane, tplane, y + 3, w0, offL, offR, lok, rok);
        emit_row(rA, rB, rC, acc0, acc1); ++y;
        derive(rA, q0, cc4); load_row(q0, plane, tplane, y + 3, w0, offL, offR, lok, rok);
        emit_row(rB, rC, rA, acc0, acc1); ++y;
        derive(rB, q1, cc4); load_row(q1, plane, tplane, y + 3, w0, offL, offR, lok, rok);
        emit_row(rC, rA, rB, acc0, acc1); ++y;
    }
    // Epilogue: rows h0+60..63; loads reach exactly row h0+64 (bottom halo)
    derive(rC, q0, cc4); load_row(q0, plane, tplane, y + 3, w0, offL, offR, lok, rok);
    emit_row(rA, rB, rC, acc0, acc1); ++y;
    derive(rA, q1, cc4); load_row(q1, plane, tplane, y + 3, w0, offL, offR, lok, rok);
    emit_row(rB, rC, rA, acc0, acc1); ++y;
    derive(rB, q0, cc4); emit_row(rC, rA, rB, acc0, acc1); ++y;
    derive(rC, q1, cc4); emit_row(rA, rB, rC, acc0, acc1);

    // reduce: warp -> block -> global double; last block finalizes + resets.
    float acc = acc0 + acc1;
    #pragma unroll
    for (int o = 16; o; o >>= 1) acc += __shfl_xor_sync(0xffffffffu, acc, o);
    __shared__ float ws[WPB];
    if (lane == 0) ws[threadIdx.x >> 5] = acc;
    __syncthreads();
    if (threadIdx.x == 0) {
        double s = 0.0;
        #pragma unroll
        for (int i = 0; i < WPB; i++) s += (double)ws[i];
        atomicAdd(&g_acc, s);
        __threadfence();
        unsigned t = atomicAdd(&g_ticket, 1u);
        if (t == (unsigned)(NBLOCKS - 1)) {
            double v = atomicAdd(&g_acc, 0.0);   // ordered read
            out[0] = (float)(v * (1.0 / ((double)BB * HH * WW)));
            g_acc = 0.0;                          // reset for next replay
            g_ticket = 0u;
        }
    }
}

// ---------------------------------------------------------------------------
extern "C" void kernel_launch(void* const* d_in, const int* in_sizes, int n_in,
                              void* d_out, int out_size)
{
    const float* inp;
    const unsigned int* tgt;
    if (in_sizes[0] == BB * CC * HH * WW) {
        inp = (const float*)d_in[0];
        tgt = (const unsigned int*)d_in[1];
    } else {
        inp = (const float*)d_in[1];
        tgt = (const unsigned int*)d_in[0];
    }
    float* out = (float*)d_out;

    prep_kernel<<<1184, 256>>>(tgt);
    edge_kernel<<<NBLOCKS, WPB * 32>>>(inp, out);
}

// round 10
// speedup vs baseline: 1.3999x; 1.0731x over previous
#include <cuda_runtime.h>
#include <stdint.h>

#define BB 16
#define CC 19
#define HH 512
#define WW 512
#define KX 4
#define WSEG 4            // 512 / (32*KX)
#define HCH 8
#define HROWS (HH/HCH)    // 64
#define WPB 4             // warps per block (128 threads)
#define NWARPS (BB*CC*WSEG*HCH)   // 9728
#define NBLOCKS (NWARPS/WPB)      // 2432

#define B01   0x01010101u

__device__ unsigned char g_tgt8[BB*HH*WW];  // 4 MB scratch (static, allowed)
__device__ double g_acc;                     // zero-init; edge's last block resets
__device__ unsigned g_ticket;

// ---------------------------------------------------------------------------
// prep: detect int64-vs-int32 targets and convert to uint8 (L2-resident for
// the 19x channel reuse). Sampling safe for the SMALLEST possible buffer
// (int32: 4,194,304 words). int64 -> all odd words zero; int32 -> odd words
// are labels, P(all 16 samples == 0) = 19^-16 ~ 0.
// ---------------------------------------------------------------------------
__global__ void prep_kernel(const unsigned int* __restrict__ t) {
    bool is32 = false;
    #pragma unroll
    for (unsigned k = 0; k < 16; k++) {
        unsigned idx = k * 262139u + 1u;       // max 3,932,086 < 4,194,304
        is32 |= (__ldg(&t[idx | 1u]) != 0u);   // force odd
    }

    const int n4 = BB * HH * WW / 4;
    for (int i = blockIdx.x * blockDim.x + threadIdx.x; i < n4;
         i += gridDim.x * blockDim.x) {
        uchar4 o;
        if (is32) {
            uint4 v = reinterpret_cast<const uint4*>(t)[i];
            o.x = (unsigned char)v.x; o.y = (unsigned char)v.y;
            o.z = (unsigned char)v.z; o.w = (unsigned char)v.w;
        } else {
            o.x = (unsigned char)t[(4 * i + 0) * 2];
            o.y = (unsigned char)t[(4 * i + 1) * 2];
            o.z = (unsigned char)t[(4 * i + 2) * 2];
            o.w = (unsigned char)t[(4 * i + 3) * 2];
        }
        reinterpret_cast<uchar4*>(g_tgt8)[i] = o;
    }
}

// ---------------------------------------------------------------------------
// Raw row (loads only; halos via direct L1-hit neighbor loads, no shuffles)
// and derived per-row separable terms.
// Target terms byte-packed: u biased +1 per byte (in [0,2]), v in [0,4].
// ---------------------------------------------------------------------------
struct Raw  { float x0, x1, x2, x3, xl, xr; unsigned t4, th; };  // th = tl|(tr<<8)
struct RowD { float a[KX], s[KX]; unsigned u, v; };

__device__ __forceinline__ void load_row(
    Raw& r, const float* __restrict__ plane,
    const unsigned char* __restrict__ tplane,
    int row, int w0, int offL, int offR, bool lok, bool rok)
{
    if ((unsigned)row >= (unsigned)HH) {        // warp-uniform
        r.x0 = r.x1 = r.x2 = r.x3 = r.xl = r.xr = 0.f;
        r.t4 = 0xFFFFFFFFu; r.th = 0xFFFFu;     // 255 != any class
        return;
    }
    const float* xrow = plane + (size_t)row * WW;
    float4 xv = *reinterpret_cast<const float4*>(xrow + w0);
    // Neighbor-element halo loads: same L1 lines as the float4s -> hits.
    // Offsets pre-clamped in-bounds; value selected at boundaries.
    float hl = __ldg(xrow + offL);
    float hr = __ldg(xrow + offR);
    r.xl = lok ? hl : 0.f;
    r.xr = rok ? hr : 0.f;
    r.x0 = xv.x; r.x1 = xv.y; r.x2 = xv.z; r.x3 = xv.w;

    const unsigned char* trow = tplane + (size_t)row * WW;
    unsigned t4 = *reinterpret_cast<const unsigned*>(trow + w0);
    unsigned tl = (unsigned)__ldg(trow + offL);
    unsigned tr = (unsigned)__ldg(trow + offR);
    r.t4 = t4;
    r.th = (lok ? tl : 0xFFu) | ((rok ? tr : 0xFFu) << 8);
}

__device__ __forceinline__ void derive(RowD& d, const Raw& r, unsigned cc4) {
    // input: diff-x / smooth-x
    d.a[0] = r.x1 - r.xl;  d.a[1] = r.x2 - r.x0;
    d.a[2] = r.x3 - r.x1;  d.a[3] = r.xr - r.x2;
    d.s[0] = fmaf(2.f, r.x0, r.xl + r.x1);
    d.s[1] = fmaf(2.f, r.x1, r.x0 + r.x2);
    d.s[2] = fmaf(2.f, r.x2, r.x1 + r.x3);
    d.s[3] = fmaf(2.f, r.x3, r.x2 + r.xr);
    // target: 2 byte-compares (center word + halo word), then PERMUTE THE
    // MASKS to build the shifted windows (saves a 3rd emulated compare).
    unsigned m01 = __vcmpeq4(r.t4, cc4) & B01;            // masks of t0..t3
    unsigned mh  = __vcmpeq4(r.th, cc4) & 0x00000101u;    // b0=ml, b1=mr
    unsigned ml01 = __byte_perm(m01, mh, 0x2104);  // (ml, m0, m1, m2)
    unsigned mr01 = __byte_perm(m01, mh, 0x5321);  // (m1, m2, m3, mr)
    d.u = (mr01 + B01) - ml01;            // per-byte u+1, in [0,2]; no borrow
    d.v = ml01 + mr01 + m01 * 2u;         // per-byte, in [0,4]; IMAD-friendly
}

__device__ __forceinline__ float unpack_b(unsigned w, unsigned sel) {
    // byte -> exact float via mantissa insertion; subtract (2^23 + bias 4)
    return __uint_as_float(__byte_perm(w, 0x4B000000u, sel)) - 8388612.0f;
}

__device__ __forceinline__ void emit_row(
    const RowD& P, const RowD& C0, const RowD& N, float& acc0, float& acc1)
{
    // packed target gradients, per-byte biased by +4, range [0,8]: carry-free
    unsigned gxt_b = C0.u * 2u + P.u + N.u;     // IMAD + IADD3
    unsigned gyt_b = (N.v + 0x04040404u) - P.v;
    #pragma unroll
    for (int i = 0; i < KX; i++) {
        float gx  = fmaf(2.f, C0.a[i], P.a[i] + N.a[i]);
        float gy  = N.s[i] - P.s[i];
        float ein = fabsf(gx) + fabsf(gy);
        unsigned sel = 0x7440u + (unsigned)i;
        float etg = fabsf(unpack_b(gxt_b, sel)) + fabsf(unpack_b(gyt_b, sel));
        float d = ein - etg;
        if (i & 1) acc1 = fmaf(d, d, acc1);
        else       acc0 = fmaf(d, d, acc0);
    }
}

__global__ __launch_bounds__(WPB * 32, 7)
void edge_kernel(const float* __restrict__ inp, float* __restrict__ out)
{
    const int warp = blockIdx.x * WPB + (threadIdx.x >> 5);
    const int lane = threadIdx.x & 31;

    const int wseg = warp & (WSEG - 1);
    const int hch  = (warp >> 2) & (HCH - 1);
    const int t2   = warp >> 5;               // = b*CC + c, in [0, 304)
    const unsigned c = (unsigned)(t2 % CC);
    const int b    = t2 / CC;
    const unsigned cc4 = c * 0x01010101u;

    const int wstart = wseg * (32 * KX);
    const int w0 = wstart + lane * KX;
    const bool lok = (w0 > 0);
    const bool rok = (w0 + KX < WW);
    const int offL = lok ? (w0 - 1)  : w0;    // clamped in-bounds
    const int offR = rok ? (w0 + KX) : w0;
    const int h0 = hch * HROWS;
    const float* plane = inp + ((size_t)t2) * HH * WW;
    const unsigned char* tplane = g_tgt8 + (size_t)b * HH * WW;

    float acc0 = 0.f, acc1 = 0.f;
    RowD rA, rB, rC;
    Raw q0, q1;

    // Prologue: invariant at loop top — q0 holds row y+1, q1 holds row y+2.
    load_row(q0, plane, tplane, h0 - 1, w0, offL, offR, lok, rok);
    load_row(q1, plane, tplane, h0,     w0, offL, offR, lok, rok);
    derive(rA, q0, cc4); load_row(q0, plane, tplane, h0 + 1, w0, offL, offR, lok, rok);
    derive(rB, q1, cc4); load_row(q1, plane, tplane, h0 + 2, w0, offL, offR, lok, rok);

    int y = h0;
    // 6-phase body (LCM of 2 raw slots x 3 row regs), 10 iters = 60 rows
    #pragma unroll 1
    for (int it = 0; it < 10; ++it) {
        derive(rC, q0, cc4); load_row(q0, plane, tplane, y + 3, w0, offL, offR, lok, rok);
        emit_row(rA, rB, rC, acc0, acc1); ++y;
        derive(rA, q1, cc4); load_row(q1, plane, tplane, y + 3, w0, offL, offR, lok, rok);
        emit_row(rB, rC, rA, acc0, acc1); ++y;
        derive(rB, q0, cc4); load_row(q0, plane, tplane, y + 3, w0, offL, offR, lok, rok);
        emit_row(rC, rA, rB, acc0, acc1); ++y;
        derive(rC, q1, cc4); load_row(q1, plane, tplane, y + 3, w0, offL, offR, lok, rok);
        emit_row(rA, rB, rC, acc0, acc1); ++y;
        derive(rA, q0, cc4); load_row(q0, plane, tplane, y + 3, w0, offL, offR, lok, rok);
        emit_row(rB, rC, rA, acc0, acc1); ++y;
        derive(rB, q1, cc4); load_row(q1, plane, tplane, y + 3, w0, offL, offR, lok, rok);
        emit_row(rC, rA, rB, acc0, acc1); ++y;
    }
    // Epilogue: rows h0+60..63; loads reach exactly row h0+64 (bottom halo)
    derive(rC, q0, cc4); load_row(q0, plane, tplane, y + 3, w0, offL, offR, lok, rok);
    emit_row(rA, rB, rC, acc0, acc1); ++y;
    derive(rA, q1, cc4); load_row(q1, plane, tplane, y + 3, w0, offL, offR, lok, rok);
    emit_row(rB, rC, rA, acc0, acc1); ++y;
    derive(rB, q0, cc4); emit_row(rC, rA, rB, acc0, acc1); ++y;
    derive(rC, q1, cc4); emit_row(rA, rB, rC, acc0, acc1);

    // reduce: warp -> block -> global double; last block finalizes + resets.
    float acc = acc0 + acc1;
    #pragma unroll
    for (int o = 16; o; o >>= 1) acc += __shfl_xor_sync(0xffffffffu, acc, o);
    __shared__ float ws[WPB];
    if (lane == 0) ws[threadIdx.x >> 5] = acc;
    __syncthreads();
    if (threadIdx.x == 0) {
        double s = 0.0;
        #pragma unroll
        for (int i = 0; i < WPB; i++) s += (double)ws[i];
        atomicAdd(&g_acc, s);
        __threadfence();
        unsigned t = atomicAdd(&g_ticket, 1u);
        if (t == (unsigned)(NBLOCKS - 1)) {
            double v = atomicAdd(&g_acc, 0.0);   // ordered read
            out[0] = (float)(v * (1.0 / ((double)BB * HH * WW)));
            g_acc = 0.0;                          // reset for next replay
            g_ticket = 0u;
        }
    }
}

// ---------------------------------------------------------------------------
extern "C" void kernel_launch(void* const* d_in, const int* in_sizes, int n_in,
                              void* d_out, int out_size)
{
    const float* inp;
    const unsigned int* tgt;
    if (in_sizes[0] == BB * CC * HH * WW) {
        inp = (const float*)d_in[0];
        tgt = (const unsigned int*)d_in[1];
    } else {
        inp = (const float*)d_in[1];
        tgt = (const unsigned int*)d_in[0];
    }
    float* out = (float*)d_out;

    prep_kernel<<<1184, 256>>>(tgt);
    edge_kernel<<<NBLOCKS, WPB * 32>>>(inp, out);
}